// round 6
// baseline (speedup 1.0000x reference)
#include <cuda_runtime.h>
#include <cuda_bf16.h>

// ---------------------------------------------------------------------------
// RelationalKENN — single persistent fused kernel.
//   Phase 1 (per node): u = unary + unary-enhance; write up (all 16 cols),
//                       stash u[0..3] in g_u4 (1.6 MB, L2-resident).
//   Ticket grid-barrier (all blocks co-resident by construction).
//   Phase 2 (per edge, grid-strided): 3-way softmax per binary clause,
//       bp = binary + db (coalesced), du1/du2 scatter via red.global.add.v4.f32.
// Lessons carried: TLP > ILP (R3), vector REDG (R2), PDL harmful (R5).
// ---------------------------------------------------------------------------

#define MAX_NODES 100000
#define THREADS   256
#define BLK_PER_SM 6
#define NUM_SMS   148
#define NBLOCKS   (NUM_SMS * BLK_PER_SM)   // 888 — all resident: 1536 thr/SM, smem 0

__device__ float g_u4[MAX_NODES * 4];            // u columns 0..3 per node
__device__ unsigned long long g_bar = 0;          // monotone barrier counter

__device__ __forceinline__ void grid_barrier()
{
    __syncthreads();
    if (threadIdx.x == 0) {
        __threadfence();                                      // release phase-1 writes
        unsigned long long ticket = atomicAdd(&g_bar, 1ULL);
        unsigned long long target = ticket - (ticket % NBLOCKS) + NBLOCKS;
        while (*(volatile unsigned long long*)&g_bar < target) {
            __nanosleep(64);
        }
        __threadfence();                                      // acquire
    }
    __syncthreads();
}

__device__ __forceinline__ void red_add_v4(float* ptr, float a, float b,
                                           float c, float d)
{
    asm volatile("red.global.add.v4.f32 [%0], {%1, %2, %3, %4};"
                 :: "l"(ptr), "f"(a), "f"(b), "f"(c), "f"(d)
                 : "memory");
}

__global__ __launch_bounds__(THREADS, BLK_PER_SM)
void kenn_fused_kernel(const float* __restrict__ unary,
                       const float* __restrict__ binary,
                       const int* __restrict__ index1,
                       const int* __restrict__ index2,
                       const float* __restrict__ uw,
                       const float* __restrict__ bw,
                       float* __restrict__ up_out,
                       float* __restrict__ bp_out,
                       int n_nodes, int n_edges)
{
    const int tid = blockIdx.x * THREADS + threadIdx.x;

    // ------------------------- Phase 1: unary -------------------------
    if (tid < n_nodes) {
        const int node = tid;
        const float4* p = reinterpret_cast<const float4*>(unary + (size_t)node * 16);
        float4 a = p[0], b4 = p[1], c4 = p[2], d4 = p[3];
        float x[16] = {a.x, a.y, a.z, a.w,  b4.x, b4.y, b4.z, b4.w,
                       c4.x, c4.y, c4.z, c4.w, d4.x, d4.y, d4.z, d4.w};

        float del[16];
#pragma unroll
        for (int i = 0; i < 16; i++) del[i] = 0.f;

        auto clause2 = [&](int ia, int ib, float w) {
            float s1 = 1.f / (1.f + __expf(-(x[ia] + x[ib])));
            float s0 = 1.f - s1;
            del[ia] -= w * s0;
            del[ib] += w * s1;
        };
        auto clause3 = [&](int ia, int ib, int ic, float w) {
            float e0 = __expf(-x[ia]), e1 = __expf(x[ib]), e2 = __expf(x[ic]);
            float inv = __fdividef(w, e0 + e1 + e2);
            del[ia] -= inv * e0;
            del[ib] += inv * e1;
            del[ic] += inv * e2;
        };

        clause2(0, 1,       __ldg(uw + 0));
        clause2(1, 2,       __ldg(uw + 1));
        clause3(2, 3, 4,    __ldg(uw + 2));
        clause2(4, 5,       __ldg(uw + 3));
        clause3(6, 7, 8,    __ldg(uw + 4));
        clause2(8, 9,       __ldg(uw + 5));
        clause3(10, 11, 12, __ldg(uw + 6));
        clause3(13, 14, 15, __ldg(uw + 7));

        float u[16];
#pragma unroll
        for (int i = 0; i < 16; i++) u[i] = x[i] + del[i];

        float4* o = reinterpret_cast<float4*>(up_out + (size_t)node * 16);
        o[0] = make_float4(u[0],  u[1],  u[2],  u[3]);
        o[1] = make_float4(u[4],  u[5],  u[6],  u[7]);
        o[2] = make_float4(u[8],  u[9],  u[10], u[11]);
        o[3] = make_float4(u[12], u[13], u[14], u[15]);

        reinterpret_cast<float4*>(g_u4)[node] = make_float4(u[0], u[1], u[2], u[3]);
    }

    // --------------------- barrier: phase 1 done ----------------------
    grid_barrier();

    // ------------------------- Phase 2: edges -------------------------
    const float wv0 = __ldg(bw + 0), wv1 = __ldg(bw + 1);
    const float wv2 = __ldg(bw + 2), wv3 = __ldg(bw + 3);
    const float wv[4] = {wv0, wv1, wv2, wv3};

    const int stride = NBLOCKS * THREADS;
    for (int e = tid; e < n_edges; e += stride) {
        int i1 = __ldg(index1 + e);
        int i2 = __ldg(index2 + e);

        float4 u1 = __ldg(reinterpret_cast<const float4*>(g_u4) + i1);
        float4 u2 = __ldg(reinterpret_cast<const float4*>(g_u4) + i2);
        float4 bv = __ldg(reinterpret_cast<const float4*>(binary) + e);

        float b[4]  = {bv.x, bv.y, bv.z, bv.w};
        float a1[4] = {u1.x, u1.y, u1.z, u1.w};
        float a2[4] = {u2.x, u2.y, u2.z, u2.w};

        float du1[4], du2[4], bpv[4];
#pragma unroll
        for (int i = 0; i < 4; i++) {
            // clause i: sel = [-u1[i], -binary[i], +u2[i]], signs [-1,-1,+1]
            float e0 = __expf(-a1[i]), e1 = __expf(-b[i]), e2 = __expf(a2[i]);
            float inv = __fdividef(wv[i], e0 + e1 + e2);
            du1[i] = -inv * e0;
            du2[i] =  inv * e2;
            bpv[i] = b[i] - inv * e1;
        }

        reinterpret_cast<float4*>(bp_out)[e] =
            make_float4(bpv[0], bpv[1], bpv[2], bpv[3]);

        // fire-and-forget; overlaps next iteration's loads
        red_add_v4(up_out + (size_t)i1 * 16, du1[0], du1[1], du1[2], du1[3]);
        red_add_v4(up_out + (size_t)i2 * 16, du2[0], du2[1], du2[2], du2[3]);
    }
}

extern "C" void kernel_launch(void* const* d_in, const int* in_sizes, int n_in,
                              void* d_out, int out_size)
{
    const float* unary   = (const float*)d_in[0];
    const float* binary  = (const float*)d_in[1];
    const int*   index1  = (const int*)d_in[2];
    const int*   index2  = (const int*)d_in[3];
    const float* uw      = (const float*)d_in[4];
    const float* bw      = (const float*)d_in[5];

    int n_nodes = in_sizes[0] / 16;
    int n_edges = in_sizes[1] / 4;

    float* up = (float*)d_out;
    float* bp = up + (size_t)n_nodes * 16;

    kenn_fused_kernel<<<NBLOCKS, THREADS>>>(unary, binary, index1, index2,
                                            uw, bw, up, bp, n_nodes, n_edges);
}

// round 7
// speedup vs baseline: 1.5804x; 1.5804x over previous
#include <cuda_runtime.h>
#include <cuda_bf16.h>

// ---------------------------------------------------------------------------
// RelationalKENN — two kernels (fusion measured 1.7x WORSE in R6; PDL worse
// in R5; thread-coarsening worse in R3 — this structure is the winner).
//   unary:  u = unary + enhance -> up (16 cols) + g_u4 stash (cols 0..3)
//   binary: per edge, 4x 3-way softmax; bp = binary + db (streaming store);
//           du1/du2 scattered via red.global.add.v4.f32 (REDG.128).
// Binary is at ~85% of the L1tex scattered-wavefront floor; tweaks here are
// feeding-path only: float4 weight load, streaming cache hints (__ldcs/__stcs)
// on read-once/write-once data, REDGs fired before the bp tail.
// ---------------------------------------------------------------------------

#define MAX_NODES 100000

__device__ float g_u4[MAX_NODES * 4];   // u columns 0..3, packed per node

__global__ void unary_kernel(const float* __restrict__ unary,
                             const float* __restrict__ uw,
                             float* __restrict__ up_out,
                             int n_nodes)
{
    int node = blockIdx.x * blockDim.x + threadIdx.x;
    if (node >= n_nodes) return;

    const float4* p = reinterpret_cast<const float4*>(unary + (size_t)node * 16);
    float4 a = p[0], b4 = p[1], c4 = p[2], d4 = p[3];
    float x[16] = {a.x, a.y, a.z, a.w,  b4.x, b4.y, b4.z, b4.w,
                   c4.x, c4.y, c4.z, c4.w, d4.x, d4.y, d4.z, d4.w};

    float del[16];
#pragma unroll
    for (int i = 0; i < 16; i++) del[i] = 0.f;

    auto clause2 = [&](int ia, int ib, float w) {
        float s1 = 1.f / (1.f + __expf(-(x[ia] + x[ib])));
        float s0 = 1.f - s1;
        del[ia] -= w * s0;
        del[ib] += w * s1;
    };
    auto clause3 = [&](int ia, int ib, int ic, float w) {
        float e0 = __expf(-x[ia]), e1 = __expf(x[ib]), e2 = __expf(x[ic]);
        float inv = __fdividef(w, e0 + e1 + e2);
        del[ia] -= inv * e0;
        del[ib] += inv * e1;
        del[ic] += inv * e2;
    };

    clause2(0, 1,       __ldg(uw + 0));
    clause2(1, 2,       __ldg(uw + 1));
    clause3(2, 3, 4,    __ldg(uw + 2));
    clause2(4, 5,       __ldg(uw + 3));
    clause3(6, 7, 8,    __ldg(uw + 4));
    clause2(8, 9,       __ldg(uw + 5));
    clause3(10, 11, 12, __ldg(uw + 6));
    clause3(13, 14, 15, __ldg(uw + 7));

    float u[16];
#pragma unroll
    for (int i = 0; i < 16; i++) u[i] = x[i] + del[i];

    float4* o = reinterpret_cast<float4*>(up_out + (size_t)node * 16);
    o[0] = make_float4(u[0],  u[1],  u[2],  u[3]);
    o[1] = make_float4(u[4],  u[5],  u[6],  u[7]);
    o[2] = make_float4(u[8],  u[9],  u[10], u[11]);
    o[3] = make_float4(u[12], u[13], u[14], u[15]);

    reinterpret_cast<float4*>(g_u4)[node] = make_float4(u[0], u[1], u[2], u[3]);
}

__device__ __forceinline__ void red_add_v4(float* ptr, float a, float b,
                                           float c, float d)
{
    asm volatile("red.global.add.v4.f32 [%0], {%1, %2, %3, %4};"
                 :: "l"(ptr), "f"(a), "f"(b), "f"(c), "f"(d)
                 : "memory");
}

__global__ __launch_bounds__(256)
void binary_kernel(const float* __restrict__ binary,
                   const int* __restrict__ index1,
                   const int* __restrict__ index2,
                   const float* __restrict__ bw,
                   float* __restrict__ up_out,
                   float* __restrict__ bp_out,
                   int n_edges)
{
    int e = blockIdx.x * blockDim.x + threadIdx.x;
    if (e >= n_edges) return;

    // Coalesced index loads, then both random gathers back-to-back so they
    // overlap in the L1tex queue. Read-once streams use evict-first (.cs).
    int i1 = __ldg(index1 + e);
    int i2 = __ldg(index2 + e);

    float4 u1 = __ldg(reinterpret_cast<const float4*>(g_u4) + i1);
    float4 u2 = __ldg(reinterpret_cast<const float4*>(g_u4) + i2);
    float4 bv = __ldcs(reinterpret_cast<const float4*>(binary) + e);

    float4 wq = __ldg(reinterpret_cast<const float4*>(bw));
    float wv[4] = {wq.x, wq.y, wq.z, wq.w};

    float b[4]  = {bv.x, bv.y, bv.z, bv.w};
    float a1[4] = {u1.x, u1.y, u1.z, u1.w};
    float a2[4] = {u2.x, u2.y, u2.z, u2.w};

    float du1[4], du2[4], ie1[4];
#pragma unroll
    for (int i = 0; i < 4; i++) {
        // clause i: sel = [-u1[i], -binary[i], +u2[i]], signs [-1,-1,+1]
        float e0 = __expf(-a1[i]), e1 = __expf(-b[i]), e2 = __expf(a2[i]);
        float inv = __fdividef(wv[i], e0 + e1 + e2);
        du1[i] = -inv * e0;
        du2[i] =  inv * e2;
        ie1[i] =  inv * e1;
    }

    // Fire the scattered fire-and-forget reductions first...
    red_add_v4(up_out + (size_t)i1 * 16, du1[0], du1[1], du1[2], du1[3]);
    red_add_v4(up_out + (size_t)i2 * 16, du2[0], du2[1], du2[2], du2[3]);

    // ...then the cheap coalesced tail, streamed past L2 (never re-read).
    __stcs(reinterpret_cast<float4*>(bp_out) + e,
           make_float4(b[0] - ie1[0], b[1] - ie1[1],
                       b[2] - ie1[2], b[3] - ie1[3]));
}

extern "C" void kernel_launch(void* const* d_in, const int* in_sizes, int n_in,
                              void* d_out, int out_size)
{
    const float* unary   = (const float*)d_in[0];
    const float* binary  = (const float*)d_in[1];
    const int*   index1  = (const int*)d_in[2];
    const int*   index2  = (const int*)d_in[3];
    const float* uw      = (const float*)d_in[4];
    const float* bw      = (const float*)d_in[5];

    int n_nodes = in_sizes[0] / 16;
    int n_edges = in_sizes[1] / 4;

    float* up = (float*)d_out;
    float* bp = up + (size_t)n_nodes * 16;

    unary_kernel<<<(n_nodes + 255) / 256, 256>>>(unary, uw, up, n_nodes);
    binary_kernel<<<(n_edges + 255) / 256, 256>>>(binary, index1, index2, bw,
                                                  up, bp, n_edges);
}

// round 8
// speedup vs baseline: 1.6990x; 1.0751x over previous
#include <cuda_runtime.h>
#include <cuda_bf16.h>

// ---------------------------------------------------------------------------
// RelationalKENN — two kernels. Measured-out alternatives: thread-coarsening
// (R3, -7%), PDL (R5, -5%), persistent fusion (R6, -70%), cache-hint/reorder
// tweaks (R7, -7%). This is the R4 optimum shape: 1 edge/thread, vector REDG,
// coalesced store first + fire-and-forget scatters last. Only delta vs R4:
// binary blockDim 512 (halves block churn/tail, same occupancy ceiling).
// ---------------------------------------------------------------------------

#define MAX_NODES 100000

__device__ float g_u4[MAX_NODES * 4];   // u columns 0..3, packed per node

__global__ void unary_kernel(const float* __restrict__ unary,
                             const float* __restrict__ uw,
                             float* __restrict__ up_out,
                             int n_nodes)
{
    int node = blockIdx.x * blockDim.x + threadIdx.x;
    if (node >= n_nodes) return;

    const float4* p = reinterpret_cast<const float4*>(unary + (size_t)node * 16);
    float4 a = p[0], b4 = p[1], c4 = p[2], d4 = p[3];
    float x[16] = {a.x, a.y, a.z, a.w,  b4.x, b4.y, b4.z, b4.w,
                   c4.x, c4.y, c4.z, c4.w, d4.x, d4.y, d4.z, d4.w};

    float del[16];
#pragma unroll
    for (int i = 0; i < 16; i++) del[i] = 0.f;

    auto clause2 = [&](int ia, int ib, float w) {
        float s1 = 1.f / (1.f + __expf(-(x[ia] + x[ib])));
        float s0 = 1.f - s1;
        del[ia] -= w * s0;
        del[ib] += w * s1;
    };
    auto clause3 = [&](int ia, int ib, int ic, float w) {
        float e0 = __expf(-x[ia]), e1 = __expf(x[ib]), e2 = __expf(x[ic]);
        float inv = __fdividef(w, e0 + e1 + e2);
        del[ia] -= inv * e0;
        del[ib] += inv * e1;
        del[ic] += inv * e2;
    };

    clause2(0, 1,       __ldg(uw + 0));
    clause2(1, 2,       __ldg(uw + 1));
    clause3(2, 3, 4,    __ldg(uw + 2));
    clause2(4, 5,       __ldg(uw + 3));
    clause3(6, 7, 8,    __ldg(uw + 4));
    clause2(8, 9,       __ldg(uw + 5));
    clause3(10, 11, 12, __ldg(uw + 6));
    clause3(13, 14, 15, __ldg(uw + 7));

    float u[16];
#pragma unroll
    for (int i = 0; i < 16; i++) u[i] = x[i] + del[i];

    float4* o = reinterpret_cast<float4*>(up_out + (size_t)node * 16);
    o[0] = make_float4(u[0],  u[1],  u[2],  u[3]);
    o[1] = make_float4(u[4],  u[5],  u[6],  u[7]);
    o[2] = make_float4(u[8],  u[9],  u[10], u[11]);
    o[3] = make_float4(u[12], u[13], u[14], u[15]);

    reinterpret_cast<float4*>(g_u4)[node] = make_float4(u[0], u[1], u[2], u[3]);
}

__device__ __forceinline__ void red_add_v4(float* ptr, float a, float b,
                                           float c, float d)
{
    asm volatile("red.global.add.v4.f32 [%0], {%1, %2, %3, %4};"
                 :: "l"(ptr), "f"(a), "f"(b), "f"(c), "f"(d)
                 : "memory");
}

__global__ __launch_bounds__(512)
void binary_kernel(const float* __restrict__ binary,
                   const int* __restrict__ index1,
                   const int* __restrict__ index2,
                   const float* __restrict__ bw,
                   float* __restrict__ up_out,
                   float* __restrict__ bp_out,
                   int n_edges)
{
    int e = blockIdx.x * blockDim.x + threadIdx.x;
    if (e >= n_edges) return;

    // Coalesced index loads first, then both random gathers back-to-back
    // so they overlap in the L1tex queue.
    int i1 = __ldg(index1 + e);
    int i2 = __ldg(index2 + e);

    float4 u1 = __ldg(reinterpret_cast<const float4*>(g_u4) + i1);
    float4 u2 = __ldg(reinterpret_cast<const float4*>(g_u4) + i2);
    float4 bv = __ldg(reinterpret_cast<const float4*>(binary) + e);

    float wv[4] = {__ldg(bw + 0), __ldg(bw + 1), __ldg(bw + 2), __ldg(bw + 3)};

    float b[4]  = {bv.x, bv.y, bv.z, bv.w};
    float a1[4] = {u1.x, u1.y, u1.z, u1.w};
    float a2[4] = {u2.x, u2.y, u2.z, u2.w};

    float du1[4], du2[4], bpv[4];
#pragma unroll
    for (int i = 0; i < 4; i++) {
        // clause i: sel = [-u1[i], -binary[i], +u2[i]], signs [-1,-1,+1]
        float e0 = __expf(-a1[i]), e1 = __expf(-b[i]), e2 = __expf(a2[i]);
        float inv = __fdividef(wv[i], e0 + e1 + e2);
        du1[i] = -inv * e0;
        du2[i] =  inv * e2;
        bpv[i] = b[i] - inv * e1;
    }

    // Coalesced stream store first, fire-and-forget scatters last so the
    // warp has no outstanding dependences when it retires.
    reinterpret_cast<float4*>(bp_out)[e] = make_float4(bpv[0], bpv[1], bpv[2], bpv[3]);

    red_add_v4(up_out + (size_t)i1 * 16, du1[0], du1[1], du1[2], du1[3]);
    red_add_v4(up_out + (size_t)i2 * 16, du2[0], du2[1], du2[2], du2[3]);
}

extern "C" void kernel_launch(void* const* d_in, const int* in_sizes, int n_in,
                              void* d_out, int out_size)
{
    const float* unary   = (const float*)d_in[0];
    const float* binary  = (const float*)d_in[1];
    const int*   index1  = (const int*)d_in[2];
    const int*   index2  = (const int*)d_in[3];
    const float* uw      = (const float*)d_in[4];
    const float* bw      = (const float*)d_in[5];

    int n_nodes = in_sizes[0] / 16;
    int n_edges = in_sizes[1] / 4;

    float* up = (float*)d_out;
    float* bp = up + (size_t)n_nodes * 16;

    unary_kernel<<<(n_nodes + 255) / 256, 256>>>(unary, uw, up, n_nodes);
    binary_kernel<<<(n_edges + 511) / 512, 512>>>(binary, index1, index2, bw,
                                                  up, bp, n_edges);
}